// round 2
// baseline (speedup 1.0000x reference)
#include <cuda_runtime.h>
#include <cuda_bf16.h>

// FineMatching: P=512 proposals, R=S=128, K=3 top-k per row/col,
// THRESHOLD=0.05, MUTUAL=false (OR), CONDITIONAL=true (scale by node score).
//
// Per proposal:
//   e = exp(x)                                   [128,128]
//   rowT[r] = 3rd-largest of e[r,:]
//   colT[s] = 3rd-largest of e[:,s]
//   in_row = e >= rowT[r]; in_col = e >= colT[s]
//   score = 0.5*ncs[p]*e*(in_row+in_col)
//   corr  = (in_row|in_col) & (e>0.05) & refm[r] & srcm[s]
//
// Masks arrive as 32-bit words (bool widened by the harness); "true" iff the
// 32-bit pattern is nonzero — correct for both int32 (1) and float32 (1.0f).
//
// Memory-bound: ~100MB of HBM traffic total. One CTA per proposal keeps the
// 64KB exp-tile in smem (stride-129 padding -> conflict-free row AND col scans).

#define PP 512
#define RR 128
#define SS 128
#define STRIDE 129          // 129 % 32 = 1 -> bank (r+i)%32, conflict-free both ways
#define NTHREADS 256
#define THRESH 0.05f

__global__ __launch_bounds__(NTHREADS) void fine_matching_kernel(
    const float* __restrict__ msm,          // [P,R,S] log scores
    const unsigned int* __restrict__ refm,  // [P,R] bool widened to 32-bit
    const unsigned int* __restrict__ srcm,  // [P,S] bool widened to 32-bit
    const float* __restrict__ ncs,          // [P]
    float* __restrict__ out,                // [P*R*S score | P*R*S corr]
    int write_corr)
{
    extern __shared__ float sh[];
    float* e    = sh;                    // [RR * STRIDE]
    float* rowT = sh + RR * STRIDE;      // [RR]
    float* colT = rowT + RR;             // [SS]

    const int p   = blockIdx.x;
    const int tid = threadIdx.x;
    const float* g = msm + (size_t)p * (RR * SS);

    // ---- Phase 1: load + exp into padded smem (coalesced LDG, conflict-free STS)
    #pragma unroll 4
    for (int i = tid; i < RR * SS; i += NTHREADS) {
        int r = i >> 7;
        int c = i & 127;
        e[r * STRIDE + c] = __expf(g[i]);
    }
    __syncthreads();

    // ---- Phase 2: top-3 thresholds. Threads 0..127 scan rows, 128..255 scan cols.
    // Branch-free sorted-3 insert: 5 min/max ops per element.
    if (tid < RR) {
        const float* row = e + tid * STRIDE;
        float v1 = -1e30f, v2 = -1e30f, v3 = -1e30f;
        #pragma unroll 8
        for (int c = 0; c < SS; ++c) {
            float v  = row[c];
            float t1 = fminf(v1, v);
            float t2 = fminf(v2, v);
            v1 = fmaxf(v1, v);
            v2 = fmaxf(v2, t1);
            v3 = fmaxf(v3, t2);
        }
        rowT[tid] = v3;
    } else {
        const int s = tid - RR;
        float v1 = -1e30f, v2 = -1e30f, v3 = -1e30f;
        #pragma unroll 8
        for (int r = 0; r < RR; ++r) {
            float v  = e[r * STRIDE + s];
            float t1 = fminf(v1, v);
            float t2 = fminf(v2, v);
            v1 = fmaxf(v1, v);
            v2 = fmaxf(v2, t1);
            v3 = fmaxf(v3, t2);
        }
        colT[s] = v3;
    }
    __syncthreads();

    // ---- Phase 3: dense output pass (coalesced STG)
    const float scale = 0.5f * ncs[p];
    float* score_out = out + (size_t)p * (RR * SS);
    float* corr_out  = out + (size_t)PP * (RR * SS) + (size_t)p * (RR * SS);
    const unsigned int* rm = refm + p * RR;
    const unsigned int* sm = srcm + p * SS;

    #pragma unroll 4
    for (int i = tid; i < RR * SS; i += NTHREADS) {
        int r = i >> 7;
        int s = i & 127;
        float v = e[r * STRIDE + s];
        bool a = (v >= rowT[r]);   // in row top-3
        bool b = (v >= colT[s]);   // in col top-3
        float sc = scale * v * (float)((int)a + (int)b);
        score_out[i] = sc;
        if (write_corr) {
            bool corr = (a | b) && (v > THRESH) && (rm[r] != 0u) && (sm[s] != 0u);
            corr_out[i] = corr ? 1.0f : 0.0f;
        }
    }
}

extern "C" void kernel_launch(void* const* d_in, const int* in_sizes, int n_in,
                              void* d_out, int out_size) {
    const float* msm         = (const float*)d_in[0];
    const unsigned int* refm = (const unsigned int*)d_in[1];
    const unsigned int* srcm = (const unsigned int*)d_in[2];
    const float* ncs         = (const float*)d_in[3];
    float* out               = (float*)d_out;

    const int prs = PP * RR * SS;
    int write_corr = (out_size >= 2 * prs) ? 1 : 0;

    size_t smem = (size_t)(RR * STRIDE + RR + SS) * sizeof(float);  // ~67KB
    cudaFuncSetAttribute(fine_matching_kernel,
                         cudaFuncAttributeMaxDynamicSharedMemorySize, (int)smem);

    fine_matching_kernel<<<PP, NTHREADS, smem>>>(msm, refm, srcm, ncs, out,
                                                 write_corr);
}

// round 3
// speedup vs baseline: 1.9534x; 1.9534x over previous
#include <cuda_runtime.h>
#include <cuda_bf16.h>

// FineMatching (P=512, R=S=128, K=3, THRESH=0.05, OR-combine, conditional scale).
// Reduction: cell passes iff exp(x) >= 3rd-largest of its row and/or column.
//   score = 0.5*ncs[p]*e*(in_row+in_col)
//   corr  = (in_row|in_col) & (e>0.05) & refm[r] & srcm[s]
//
// R3 design: 512 thr/CTA, 3 CTAs/SM (48 warps), fully 128-bit vectorized,
// padded smem stride 132 floats (33 float4/row) -> conflict-free in all phases:
//   P1  STS.128: warp-uniform row, lanes cover banks 4l..4l+3       (0-conflict)
//   P2c scalar col scan, 2 thr/col, halves staggered by 4 rows      (0-conflict)
//   P2r LDS.128 row scan, 2 thr/row, halves staggered by 4 float4s  (0-conflict)
//   P3  LDS.128: warp-uniform row, lanes = banks 4l..4l+3           (0-conflict)

#define PP 512
#define NT 512
#define F4ROW 33      // 132 floats per padded row
#define THRESH 0.05f

__device__ __forceinline__ void ins3(float& v1, float& v2, float& v3, float v) {
    float t1 = fminf(v1, v);
    float t2 = fminf(v2, v);
    v1 = fmaxf(v1, v);
    v2 = fmaxf(v2, t1);
    v3 = fmaxf(v3, t2);
}

__device__ __forceinline__ void merge_xor1(float& v1, float& v2, float& v3) {
    float b1 = __shfl_xor_sync(0xffffffffu, v1, 1);
    float b2 = __shfl_xor_sync(0xffffffffu, v2, 1);
    float b3 = __shfl_xor_sync(0xffffffffu, v3, 1);
    ins3(v1, v2, v3, b1);
    ins3(v1, v2, v3, b2);
    ins3(v1, v2, v3, b3);
}

__global__ __launch_bounds__(NT, 3) void fine_matching_kernel(
    const float4* __restrict__ msm4,        // [P,R,S] as float4
    const unsigned int* __restrict__ refm,  // [P,R] 32-bit bool
    const uint4* __restrict__ srcm4,        // [P,S] 32-bit bool as uint4
    const float* __restrict__ ncs,          // [P]
    float4* __restrict__ out4,              // [score | corr] as float4
    int write_corr)
{
    extern __shared__ float4 sh4[];
    float* e            = (float*)sh4;          // [128*132]
    float* rowT         = e + 128 * 132;        // [128]
    float* colT         = rowT + 128;           // [128]
    unsigned int* rmS   = (unsigned int*)(colT + 128);  // [128]

    const int p    = blockIdx.x;
    const int tid  = threadIdx.x;
    const int lane = tid & 31;

    // ---- Phase 0/1: preload ref mask; load+exp tile (LDG.128 coalesced, STS.128)
    if (tid < 128) rmS[tid] = refm[p * 128 + tid];

    const float4* g = msm4 + p * 4096;
    #pragma unroll
    for (int k = 0; k < 8; k++) {
        int i4 = tid + k * NT;            // lanes contiguous -> 512B/warp LDG
        float4 v = g[i4];
        float4 ev = make_float4(__expf(v.x), __expf(v.y), __expf(v.z), __expf(v.w));
        sh4[(i4 >> 5) * F4ROW + lane] = ev;   // row warp-uniform, banks 4l: clean
    }
    __syncthreads();

    // ---- Phase 2: top-3 thresholds, all 512 threads active
    {
        float v1 = -1e30f, v2 = -1e30f, v3 = -1e30f;
        if (tid < 256) {
            // column scan: 2 threads per column, 64 rows each
            const int s    = tid >> 1;
            const int half = tid & 1;
            #pragma unroll 8
            for (int i = 0; i < 64; i++) {
                int r = half ? (64 + ((i + 4) & 63)) : i;   // stagger: disjoint banks
                ins3(v1, v2, v3, e[r * 132 + s]);
            }
            merge_xor1(v1, v2, v3);
            if (!half) colT[s] = v3;
        } else {
            // row scan: 2 threads per row, 64 cols each via LDS.128
            const int u    = tid - 256;
            const int r    = u >> 1;
            const int half = u & 1;
            const float4* row4 = sh4 + r * F4ROW + (half ? 16 : 0);
            #pragma unroll
            for (int j = 0; j < 16; j++) {
                int jj = half ? ((j + 4) & 15) : j;         // stagger: +16-bank offset
                float4 v = row4[jj];
                ins3(v1, v2, v3, v.x);
                ins3(v1, v2, v3, v.y);
                ins3(v1, v2, v3, v.z);
                ins3(v1, v2, v3, v.w);
            }
            merge_xor1(v1, v2, v3);
            if (!half) rowT[r] = v3;
        }
    }
    __syncthreads();

    // ---- Phase 3: dense output (LDS.128 + 2x STG.128 per iter)
    const float scale = 0.5f * ncs[p];
    float4 cT = *(const float4*)(colT + 4 * lane);   // lane's 4 col thresholds
    uint4 smv = srcm4[p * 32 + lane];                // lane's 4 src-mask words
    const float m0 = (smv.x != 0u) ? 1.f : 0.f;
    const float m1 = (smv.y != 0u) ? 1.f : 0.f;
    const float m2 = (smv.z != 0u) ? 1.f : 0.f;
    const float m3 = (smv.w != 0u) ? 1.f : 0.f;

    float4* sco = out4 + (size_t)p * 4096;
    float4* cor = out4 + (size_t)PP * 4096 + (size_t)p * 4096;

    #pragma unroll
    for (int k = 0; k < 8; k++) {
        int i4 = tid + k * NT;
        int r  = i4 >> 5;                 // warp-uniform
        float rT = rowT[r];               // smem broadcast
        float rmOK = (rmS[r] != 0u) ? 1.f : 0.f;
        float4 v = sh4[r * F4ROW + lane];

        float ax = (v.x >= rT) ? 1.f : 0.f, bx = (v.x >= cT.x) ? 1.f : 0.f;
        float ay = (v.y >= rT) ? 1.f : 0.f, by = (v.y >= cT.y) ? 1.f : 0.f;
        float az = (v.z >= rT) ? 1.f : 0.f, bz = (v.z >= cT.z) ? 1.f : 0.f;
        float aw = (v.w >= rT) ? 1.f : 0.f, bw = (v.w >= cT.w) ? 1.f : 0.f;

        float4 s4;
        s4.x = scale * v.x * (ax + bx);
        s4.y = scale * v.y * (ay + by);
        s4.z = scale * v.z * (az + bz);
        s4.w = scale * v.w * (aw + bw);
        sco[i4] = s4;

        if (write_corr) {
            float4 c4;
            c4.x = ((ax + bx > 0.f) && (v.x > THRESH)) ? rmOK * m0 : 0.f;
            c4.y = ((ay + by > 0.f) && (v.y > THRESH)) ? rmOK * m1 : 0.f;
            c4.z = ((az + bz > 0.f) && (v.z > THRESH)) ? rmOK * m2 : 0.f;
            c4.w = ((aw + bw > 0.f) && (v.w > THRESH)) ? rmOK * m3 : 0.f;
            cor[i4] = c4;
        }
    }
}

extern "C" void kernel_launch(void* const* d_in, const int* in_sizes, int n_in,
                              void* d_out, int out_size) {
    const float4* msm4       = (const float4*)d_in[0];
    const unsigned int* refm = (const unsigned int*)d_in[1];
    const uint4* srcm4       = (const uint4*)d_in[2];
    const float* ncs         = (const float*)d_in[3];
    float4* out4             = (float4*)d_out;

    const int prs = PP * 128 * 128;
    int write_corr = (out_size >= 2 * prs) ? 1 : 0;

    size_t smem = (size_t)(128 * 132 + 128 + 128) * sizeof(float)
                + 128 * sizeof(unsigned int);   // ~68.6KB
    cudaFuncSetAttribute(fine_matching_kernel,
                         cudaFuncAttributeMaxDynamicSharedMemorySize, (int)smem);

    fine_matching_kernel<<<PP, NT, smem>>>(msm4, refm, srcm4, ncs, out4,
                                           write_corr);
}

// round 4
// speedup vs baseline: 2.1740x; 1.1130x over previous
#include <cuda_runtime.h>
#include <cuda_bf16.h>

// FineMatching (P=512, R=S=128, K=3, THRESH=0.05, OR-combine, conditional scale).
//   e = exp(x); rowT[r]/colT[s] = 3rd-largest of row/col
//   score = 0.5*ncs[p]*e*((e>=rowT)+(e>=colT))
//   corr  = ((e>=rowT)|(e>=colT)) & (e>0.05) & refm[r] & srcm[s]
//
// R4: issue-bound -> cut instructions. Lockstep two-loop staggers (no per-iter
// mask ALU), pointer+imm addressing, write_corr hoisted, predicate math,
// streaming stores. Smem stride 132 floats; all phases bank-conflict-free.

#define PP 512
#define NT 512
#define THRESH 0.05f

__device__ __forceinline__ void ins3(float& v1, float& v2, float& v3, float v) {
    float t1 = fminf(v1, v);
    float t2 = fminf(v2, v);
    v1 = fmaxf(v1, v);
    v2 = fmaxf(v2, t1);
    v3 = fmaxf(v3, t2);
}

__device__ __forceinline__ void ins3_4(float& v1, float& v2, float& v3, float4 v) {
    ins3(v1, v2, v3, v.x);
    ins3(v1, v2, v3, v.y);
    ins3(v1, v2, v3, v.z);
    ins3(v1, v2, v3, v.w);
}

__device__ __forceinline__ void merge_xor1(float& v1, float& v2, float& v3) {
    float b1 = __shfl_xor_sync(0xffffffffu, v1, 1);
    float b2 = __shfl_xor_sync(0xffffffffu, v2, 1);
    float b3 = __shfl_xor_sync(0xffffffffu, v3, 1);
    ins3(v1, v2, v3, b1);
    ins3(v1, v2, v3, b2);
    ins3(v1, v2, v3, b3);
}

__global__ __launch_bounds__(NT, 3) void fine_matching_kernel(
    const float4* __restrict__ msm4,        // [P,R,S] as float4
    const unsigned int* __restrict__ refm,  // [P,R] 32-bit bool
    const uint4* __restrict__ srcm4,        // [P,S] 32-bit bool as uint4
    const float* __restrict__ ncs,          // [P]
    float4* __restrict__ out4,              // [score | corr] as float4
    int write_corr)
{
    extern __shared__ float4 sh4[];
    float* e    = (float*)sh4;           // [128*132]
    float* rowT = e + 128 * 132;         // [128]
    float* colT = rowT + 128;            // [128]
    float* rmF  = colT + 128;            // [128] ref mask as 0/1 float

    const int p    = blockIdx.x;
    const int tid  = threadIdx.x;
    const int lane = tid & 31;

    // ---- Phase 0/1: ref-mask -> float; load + exp tile (LDG.128 / STS.128)
    if (tid < 128) rmF[tid] = (refm[p * 128 + tid] != 0u) ? 1.0f : 0.0f;

    const float4* g = msm4 + p * 4096 + tid;
    float4* sp = sh4 + (tid >> 5) * 33 + lane;
    #pragma unroll
    for (int k = 0; k < 8; k++) {
        float4 v = g[k * NT];
        sp[k * 16 * 33] = make_float4(__expf(v.x), __expf(v.y),
                                      __expf(v.z), __expf(v.w));
    }
    __syncthreads();

    // ---- Phase 2: top-3 thresholds (512 threads, lockstep staggered halves)
    if (tid < 256) {
        // columns: 2 threads/col; half1 scans rows 68..127 then 64..67
        const int s    = tid >> 1;
        const int half = tid & 1;
        float v1 = -1e30f, v2 = -1e30f, v3 = -1e30f;
        const float* pa = e + (half ? 68 * 132 : 0) + s;
        #pragma unroll
        for (int j = 0; j < 60; j++) ins3(v1, v2, v3, pa[j * 132]);
        const float* pb = e + (half ? 64 * 132 : 60 * 132) + s;
        #pragma unroll
        for (int j = 0; j < 4; j++) ins3(v1, v2, v3, pb[j * 132]);
        merge_xor1(v1, v2, v3);
        if (!half) colT[s] = v3;
    } else {
        // rows: 2 threads/row via LDS.128; half1 reads f4 20..31 then 16..19
        const int u    = tid - 256;
        const int r    = u >> 1;
        const int half = u & 1;
        float v1 = -1e30f, v2 = -1e30f, v3 = -1e30f;
        const float4* ra = sh4 + r * 33 + (half ? 20 : 0);
        #pragma unroll
        for (int j = 0; j < 12; j++) ins3_4(v1, v2, v3, ra[j]);
        const float4* rb = sh4 + r * 33 + (half ? 16 : 12);
        #pragma unroll
        for (int j = 0; j < 4; j++) ins3_4(v1, v2, v3, rb[j]);
        merge_xor1(v1, v2, v3);
        if (!half) rowT[r] = v3;
    }
    __syncthreads();

    // ---- Phase 3: dense output (LDS.128 + 2x STG.128 streaming per iter)
    const float scale = 0.5f * __ldg(ncs + p);
    const float4 cT = *(const float4*)(colT + 4 * lane);
    const uint4 smv = srcm4[p * 32 + lane];
    const float m0 = (smv.x != 0u) ? 1.f : 0.f;
    const float m1 = (smv.y != 0u) ? 1.f : 0.f;
    const float m2 = (smv.z != 0u) ? 1.f : 0.f;
    const float m3 = (smv.w != 0u) ? 1.f : 0.f;

    const float4* tp  = sh4 + (tid >> 5) * 33 + lane;
    const float* rTp  = rowT + (tid >> 5);
    const float* rmp  = rmF + (tid >> 5);
    float4* sco = out4 + (size_t)p * 4096 + tid;
    float4* cor = sco + (size_t)PP * 4096;

    if (write_corr) {
        #pragma unroll
        for (int k = 0; k < 8; k++) {
            float rT = rTp[16 * k];
            float rm = rmp[16 * k];
            float4 v = tp[k * 16 * 33];

            bool ax = v.x >= rT, bx = v.x >= cT.x;
            bool ay = v.y >= rT, by = v.y >= cT.y;
            bool az = v.z >= rT, bz = v.z >= cT.z;
            bool aw = v.w >= rT, bw = v.w >= cT.w;

            float svx = scale * v.x, svy = scale * v.y;
            float svz = scale * v.z, svw = scale * v.w;

            float4 s4;
            s4.x = (ax ? svx : 0.f) + (bx ? svx : 0.f);
            s4.y = (ay ? svy : 0.f) + (by ? svy : 0.f);
            s4.z = (az ? svz : 0.f) + (bz ? svz : 0.f);
            s4.w = (aw ? svw : 0.f) + (bw ? svw : 0.f);
            __stcs(sco + k * NT, s4);

            float4 c4;
            c4.x = ((ax || bx) && v.x > THRESH) ? rm * m0 : 0.f;
            c4.y = ((ay || by) && v.y > THRESH) ? rm * m1 : 0.f;
            c4.z = ((az || bz) && v.z > THRESH) ? rm * m2 : 0.f;
            c4.w = ((aw || bw) && v.w > THRESH) ? rm * m3 : 0.f;
            __stcs(cor + k * NT, c4);
        }
    } else {
        #pragma unroll
        for (int k = 0; k < 8; k++) {
            float rT = rTp[16 * k];
            float4 v = tp[k * 16 * 33];
            bool ax = v.x >= rT, bx = v.x >= cT.x;
            bool ay = v.y >= rT, by = v.y >= cT.y;
            bool az = v.z >= rT, bz = v.z >= cT.z;
            bool aw = v.w >= rT, bw = v.w >= cT.w;
            float svx = scale * v.x, svy = scale * v.y;
            float svz = scale * v.z, svw = scale * v.w;
            float4 s4;
            s4.x = (ax ? svx : 0.f) + (bx ? svx : 0.f);
            s4.y = (ay ? svy : 0.f) + (by ? svy : 0.f);
            s4.z = (az ? svz : 0.f) + (bz ? svz : 0.f);
            s4.w = (aw ? svw : 0.f) + (bw ? svw : 0.f);
            __stcs(sco + k * NT, s4);
        }
    }
}

extern "C" void kernel_launch(void* const* d_in, const int* in_sizes, int n_in,
                              void* d_out, int out_size) {
    const float4* msm4       = (const float4*)d_in[0];
    const unsigned int* refm = (const unsigned int*)d_in[1];
    const uint4* srcm4       = (const uint4*)d_in[2];
    const float* ncs         = (const float*)d_in[3];
    float4* out4             = (float4*)d_out;

    const int prs = PP * 128 * 128;
    int write_corr = (out_size >= 2 * prs) ? 1 : 0;

    size_t smem = (size_t)(128 * 132 + 3 * 128) * sizeof(float);  // ~67.5KB
    cudaFuncSetAttribute(fine_matching_kernel,
                         cudaFuncAttributeMaxDynamicSharedMemorySize, (int)smem);

    fine_matching_kernel<<<PP, NT, smem>>>(msm4, refm, srcm4, ncs, out4,
                                           write_corr);
}